// round 9
// baseline (speedup 1.0000x reference)
#include <cuda_runtime.h>

#define VOCAB 50000
#define EDIM  128
#define HDIM  15
#define CDIM  20
#define BATCH 512
#define SEQ   512
#define WP    132            // padded W_ih smem pitch (floats)

// G table: [v][j] = {0.5*(r+bhh_r), 0.5*(z+bhh_z), n_part, 0}
__device__ float4 g_G[(size_t)VOCAB * 16];
__device__ int    g_xi[BATCH * SEQ];     // tokens converted to int32

__device__ __forceinline__ float tanhap(float x) {
    float y;
    asm("tanh.approx.f32 %0, %1;" : "=f"(y) : "f"(x));
    return y;
}
__device__ __forceinline__ int clampv(int v) { return min(max(v, 0), VOCAB - 1); }

// ---------------------------------------------------------------------------
// Kernel A: tiled gates GEMM + fused token conversion (first 256 blocks).
// ---------------------------------------------------------------------------
__global__ void __launch_bounds__(256) gates_kernel(const float* __restrict__ embed,
                                                    const float* __restrict__ W_ih,
                                                    const float* __restrict__ b_ih,
                                                    const float* __restrict__ b_hh,
                                                    const void*  __restrict__ xraw) {
    // ---- fused conv: blocks 0..255 convert 1024 tokens each ----
    if (blockIdx.x < 256) {
        __shared__ int s64;
        if (threadIdx.x == 0) {
            const int* xi = (const int*)xraw;
            int ok = 1;
            #pragma unroll
            for (int k = 0; k < 32; ++k)
                if (xi[2 * k + 1] != 0) ok = 0;   // int64 < 2^31 => high words 0
            s64 = ok;
        }
        __syncthreads();
        int i0 = (blockIdx.x * 256 + threadIdx.x) * 4;
        if (s64) {
            const longlong4 v = ((const longlong4*)xraw)[i0 >> 2];
            int4 o;
            o.x = (int)v.x; o.y = (int)v.y; o.z = (int)v.z; o.w = (int)v.w;
            *(int4*)&g_xi[i0] = o;
        } else {
            *(int4*)&g_xi[i0] = *(const int4*)((const int*)xraw + i0);
        }
    }

    // ---- gates GEMM ----
    __shared__ __align__(16) float Wsm[45 * WP];
    for (int i = threadIdx.x; i < 45 * EDIM; i += 256) {
        int r = i >> 7, c = i & 127;
        Wsm[r * WP + c] = W_ih[i];
    }
    __syncthreads();

    int rr = threadIdx.x >> 4;
    int ss = threadIdx.x & 15;
    int sw = min(ss, 14);
    int v0 = blockIdx.x * 64;

    const float4* w0p = (const float4*)&Wsm[sw * WP];
    const float4* w1p = (const float4*)&Wsm[(15 + sw) * WP];
    const float4* w2p = (const float4*)&Wsm[(30 + sw) * WP];

    const float4* ep[4];
    int vr[4];
    #pragma unroll
    for (int i = 0; i < 4; ++i) {
        vr[i] = v0 + rr + 16 * i;
        ep[i] = (const float4*)embed + (size_t)min(vr[i], VOCAB - 1) * 32;
    }

    float ar[4] = {0, 0, 0, 0}, az[4] = {0, 0, 0, 0}, an[4] = {0, 0, 0, 0};
    #pragma unroll 4
    for (int k4 = 0; k4 < 32; ++k4) {
        float4 w0 = w0p[k4], w1 = w1p[k4], w2 = w2p[k4];
        #pragma unroll
        for (int i = 0; i < 4; ++i) {
            float4 a = ep[i][k4];
            ar[i] = fmaf(a.x, w0.x, ar[i]); ar[i] = fmaf(a.y, w0.y, ar[i]);
            ar[i] = fmaf(a.z, w0.z, ar[i]); ar[i] = fmaf(a.w, w0.w, ar[i]);
            az[i] = fmaf(a.x, w1.x, az[i]); az[i] = fmaf(a.y, w1.y, az[i]);
            az[i] = fmaf(a.z, w1.z, az[i]); az[i] = fmaf(a.w, w1.w, az[i]);
            an[i] = fmaf(a.x, w2.x, an[i]); an[i] = fmaf(a.y, w2.y, an[i]);
            an[i] = fmaf(a.z, w2.z, an[i]); an[i] = fmaf(a.w, w2.w, an[i]);
        }
    }

    float bi0 = b_ih[sw] + b_hh[sw];               // fold b_hh into r,z slots
    float bi1 = b_ih[15 + sw] + b_hh[15 + sw];
    float bi2 = b_ih[30 + sw];
    #pragma unroll
    for (int i = 0; i < 4; ++i) {
        if (vr[i] < VOCAB) {
            float4 o;
            o.x = 0.5f * (ar[i] + bi0);            // pre-halved for sigmoid-via-tanh
            o.y = 0.5f * (az[i] + bi1);
            o.z = an[i] + bi2;
            o.w = 0.f;
            if (ss == 15) o = make_float4(0.f, 0.f, 0.f, 0.f);
            g_G[(size_t)vr[i] * 16 + ss] = o;
        }
    }
}

// ---------------------------------------------------------------------------
// Kernel B: GRU recurrence + fused head.
// 4 chains per warp: 2 SIMT lane-groups (16 lanes, lane j owns h[j]) x
// 2 register-interleaved chains (A/B) so chain B's instructions fill chain
// A's dependency stalls. h exchanged via width-16 shfl. G prefetched 2 steps
// ahead per chain.
// ---------------------------------------------------------------------------
__global__ void __launch_bounds__(64) rnn_kernel(const float* __restrict__ W_hh,
                                                 const float* __restrict__ b_hh,
                                                 const float* __restrict__ W_out,
                                                 const float* __restrict__ b_out,
                                                 float* __restrict__ out) {
    const unsigned FULL = 0xffffffffu;
    int j    = threadIdx.x & 15;
    int grp  = threadIdx.x >> 4;          // 0..3 (two groups per warp)
    int jj   = min(j, 14);
    int gidA = blockIdx.x * 8 + grp * 2;  // chain A
    int gidB = gidA + 1;                  // chain B

    float wr[15], wz[15], wn[15];
    #pragma unroll
    for (int k = 0; k < 15; ++k) {
        wr[k] = 0.5f * W_hh[jj * 15 + k];          // pre-halved (sigmoid-via-tanh)
        wz[k] = 0.5f * W_hh[(15 + jj) * 15 + k];
        wn[k] = W_hh[(30 + jj) * 15 + k];
    }
    const float bn = b_hh[30 + jj];

    const int* xpA = g_xi + (size_t)gidA * SEQ;
    const int* xpB = g_xi + (size_t)gidB * SEQ;
    const float4* G4 = g_G;

    float4 cA0 = G4[(size_t)clampv(xpA[0]) * 16 + j];
    float4 cA1 = G4[(size_t)clampv(xpA[1]) * 16 + j];
    float4 cB0 = G4[(size_t)clampv(xpB[0]) * 16 + j];
    float4 cB1 = G4[(size_t)clampv(xpB[1]) * 16 + j];

    float hA = 0.f, hB = 0.f;
    #pragma unroll 2
    for (int s = 0; s < SEQ; ++s) {
        int pf = (s + 2 < SEQ) ? s + 2 : SEQ - 1;
        float4 gA = G4[(size_t)clampv(xpA[pf]) * 16 + j];
        float4 gB = G4[(size_t)clampv(xpB[pf]) * 16 + j];

        float arA0 = cA0.x, arA1 = 0.f, azA0 = cA0.y, azA1 = 0.f, anA0 = bn, anA1 = 0.f;
        float arB0 = cB0.x, arB1 = 0.f, azB0 = cB0.y, azB1 = 0.f, anB0 = bn, anB1 = 0.f;
        #pragma unroll
        for (int k = 0; k < 15; ++k) {
            float hkA = __shfl_sync(FULL, hA, k, 16);
            float hkB = __shfl_sync(FULL, hB, k, 16);
            if (k & 1) {
                arA1 = fmaf(wr[k], hkA, arA1);  arB1 = fmaf(wr[k], hkB, arB1);
                azA1 = fmaf(wz[k], hkA, azA1);  azB1 = fmaf(wz[k], hkB, azB1);
                anA1 = fmaf(wn[k], hkA, anA1);  anB1 = fmaf(wn[k], hkB, anB1);
            } else {
                arA0 = fmaf(wr[k], hkA, arA0);  arB0 = fmaf(wr[k], hkB, arB0);
                azA0 = fmaf(wz[k], hkA, azA0);  azB0 = fmaf(wz[k], hkB, azB0);
                anA0 = fmaf(wn[k], hkA, anA0);  anB0 = fmaf(wn[k], hkB, anB0);
            }
        }
        float rgA = fmaf(0.5f, tanhap(arA0 + arA1), 0.5f);
        float rgB = fmaf(0.5f, tanhap(arB0 + arB1), 0.5f);
        float zgA = fmaf(0.5f, tanhap(azA0 + azA1), 0.5f);
        float zgB = fmaf(0.5f, tanhap(azB0 + azB1), 0.5f);
        float ngA = tanhap(fmaf(rgA, anA0 + anA1, cA0.z));
        float ngB = tanhap(fmaf(rgB, anB0 + anB1, cB0.z));
        hA = fmaf(zgA, hA - ngA, ngA);             // (1-z)*n + z*h
        hB = fmaf(zgB, hB - ngB, ngB);

        cA0 = cA1; cA1 = gA;
        cB0 = cB1; cB1 = gB;
    }

    // ---- fused head for both chains ----
    #pragma unroll
    for (int c = 0; c < 2; ++c) {
        float h = c ? hB : hA;
        int gid = c ? gidB : gidA;
        float l0 = b_out[j];
        float l1 = (j < 4) ? b_out[16 + j] : -3.0e38f;
        #pragma unroll
        for (int k = 0; k < 15; ++k) {
            float hk = __shfl_sync(FULL, h, k, 16);
            l0 = fmaf(W_out[j * 15 + k], hk, l0);
            if (j < 4) l1 = fmaf(W_out[(16 + j) * 15 + k], hk, l1);
        }
        float m = fmaxf(l0, l1);
        #pragma unroll
        for (int o = 8; o > 0; o >>= 1) m = fmaxf(m, __shfl_xor_sync(FULL, m, o, 16));
        float e0 = __expf(l0 - m);
        float e1 = (j < 4) ? __expf(l1 - m) : 0.f;
        float sum = e0 + e1;
        #pragma unroll
        for (int o = 8; o > 0; o >>= 1) sum += __shfl_xor_sync(FULL, sum, o, 16);
        float inv = __fdividef(1.f, sum);
        out[gid * CDIM + j] = e0 * inv;
        if (j < 4) out[gid * CDIM + 16 + j] = e1 * inv;
    }
}

// ---------------------------------------------------------------------------
extern "C" void kernel_launch(void* const* d_in, const int* in_sizes, int n_in,
                              void* d_out, int out_size) {
    const void*  x     = d_in[0];
    const float* embed = (const float*)d_in[1];
    const float* W_ih  = (const float*)d_in[2];
    const float* b_ih  = (const float*)d_in[3];
    const float* W_hh  = (const float*)d_in[4];
    const float* b_hh  = (const float*)d_in[5];
    const float* W_out = (const float*)d_in[6];
    const float* b_out = (const float*)d_in[7];
    float* out = (float*)d_out;

    gates_kernel<<<(VOCAB + 63) / 64, 256>>>(embed, W_ih, b_ih, b_hh, x);
    rnn_kernel<<<BATCH / 8, 64>>>(W_hh, b_hh, W_out, b_out, out);
}

// round 10
// speedup vs baseline: 1.5863x; 1.5863x over previous
#include <cuda_runtime.h>

#define VOCAB 50000
#define EDIM  128
#define HDIM  15
#define CDIM  20
#define BATCH 512
#define SEQ   512
#define WP    132            // padded W_ih smem pitch (floats)

// G table: [v][j] = {0.5*(r+bhh_r), 0.5*(z+bhh_z), n_part, 0}
__device__ float4 g_G[(size_t)VOCAB * 16];
__device__ int    g_xi[BATCH * SEQ];     // tokens converted to int32

typedef unsigned long long ull;

__device__ __forceinline__ float tanhap(float x) {
    float y;
    asm("tanh.approx.f32 %0, %1;" : "=f"(y) : "f"(x));
    return y;
}
__device__ __forceinline__ int clampv(int v) { return min(max(v, 0), VOCAB - 1); }

__device__ __forceinline__ ull pk(float lo, float hi) {
    ull r; asm("mov.b64 %0, {%1, %2};" : "=l"(r) : "f"(lo), "f"(hi)); return r;
}
__device__ __forceinline__ void upk(float& lo, float& hi, ull v) {
    asm("mov.b64 {%0, %1}, %2;" : "=f"(lo), "=f"(hi) : "l"(v));
}
__device__ __forceinline__ ull f2fma(ull a, ull b, ull c) {
    ull d; asm("fma.rn.f32x2 %0, %1, %2, %3;" : "=l"(d) : "l"(a), "l"(b), "l"(c)); return d;
}
__device__ __forceinline__ ull f2add(ull a, ull b) {
    ull d; asm("add.rn.f32x2 %0, %1, %2;" : "=l"(d) : "l"(a), "l"(b)); return d;
}

// ---------------------------------------------------------------------------
// Kernel A: tiled gates GEMM + fused token conversion (first 256 blocks).
// ---------------------------------------------------------------------------
__global__ void __launch_bounds__(256) gates_kernel(const float* __restrict__ embed,
                                                    const float* __restrict__ W_ih,
                                                    const float* __restrict__ b_ih,
                                                    const float* __restrict__ b_hh,
                                                    const void*  __restrict__ xraw) {
    // ---- fused conv: blocks 0..255 convert 1024 tokens each ----
    if (blockIdx.x < 256) {
        __shared__ int s64;
        if (threadIdx.x == 0) {
            const int* xi = (const int*)xraw;
            int ok = 1;
            #pragma unroll
            for (int k = 0; k < 32; ++k)
                if (xi[2 * k + 1] != 0) ok = 0;   // int64 < 2^31 => high words 0
            s64 = ok;
        }
        __syncthreads();
        int i0 = (blockIdx.x * 256 + threadIdx.x) * 4;
        if (s64) {
            const longlong4 v = ((const longlong4*)xraw)[i0 >> 2];
            int4 o;
            o.x = (int)v.x; o.y = (int)v.y; o.z = (int)v.z; o.w = (int)v.w;
            *(int4*)&g_xi[i0] = o;
        } else {
            *(int4*)&g_xi[i0] = *(const int4*)((const int*)xraw + i0);
        }
    }

    // ---- gates GEMM ----
    __shared__ __align__(16) float Wsm[45 * WP];
    for (int i = threadIdx.x; i < 45 * EDIM; i += 256) {
        int r = i >> 7, c = i & 127;
        Wsm[r * WP + c] = W_ih[i];
    }
    __syncthreads();

    int rr = threadIdx.x >> 4;
    int ss = threadIdx.x & 15;
    int sw = min(ss, 14);
    int v0 = blockIdx.x * 64;

    const float4* w0p = (const float4*)&Wsm[sw * WP];
    const float4* w1p = (const float4*)&Wsm[(15 + sw) * WP];
    const float4* w2p = (const float4*)&Wsm[(30 + sw) * WP];

    const float4* ep[4];
    int vr[4];
    #pragma unroll
    for (int i = 0; i < 4; ++i) {
        vr[i] = v0 + rr + 16 * i;
        ep[i] = (const float4*)embed + (size_t)min(vr[i], VOCAB - 1) * 32;
    }

    float ar[4] = {0, 0, 0, 0}, az[4] = {0, 0, 0, 0}, an[4] = {0, 0, 0, 0};
    #pragma unroll 4
    for (int k4 = 0; k4 < 32; ++k4) {
        float4 w0 = w0p[k4], w1 = w1p[k4], w2 = w2p[k4];
        #pragma unroll
        for (int i = 0; i < 4; ++i) {
            float4 a = ep[i][k4];
            ar[i] = fmaf(a.x, w0.x, ar[i]); ar[i] = fmaf(a.y, w0.y, ar[i]);
            ar[i] = fmaf(a.z, w0.z, ar[i]); ar[i] = fmaf(a.w, w0.w, ar[i]);
            az[i] = fmaf(a.x, w1.x, az[i]); az[i] = fmaf(a.y, w1.y, az[i]);
            az[i] = fmaf(a.z, w1.z, az[i]); az[i] = fmaf(a.w, w1.w, az[i]);
            an[i] = fmaf(a.x, w2.x, an[i]); an[i] = fmaf(a.y, w2.y, an[i]);
            an[i] = fmaf(a.z, w2.z, an[i]); an[i] = fmaf(a.w, w2.w, an[i]);
        }
    }

    float bi0 = b_ih[sw] + b_hh[sw];               // fold b_hh into r,z slots
    float bi1 = b_ih[15 + sw] + b_hh[15 + sw];
    float bi2 = b_ih[30 + sw];
    #pragma unroll
    for (int i = 0; i < 4; ++i) {
        if (vr[i] < VOCAB) {
            float4 o;
            o.x = 0.5f * (ar[i] + bi0);            // pre-halved for sigmoid-via-tanh
            o.y = 0.5f * (az[i] + bi1);
            o.z = an[i] + bi2;
            o.w = 0.f;
            if (ss == 15) o = make_float4(0.f, 0.f, 0.f, 0.f);
            g_G[(size_t)vr[i] * 16 + ss] = o;
        }
    }
}

// ---------------------------------------------------------------------------
// Kernel B: GRU recurrence + fused head (R6 structure).
// 16 lanes/chain, 8 chains/block, smem double-buffered h exchange.
// Matvecs use packed fma.rn.f32x2 across k-pairs (k padded to 16 with zero
// weights; lane-15 h is finite so 0*h15 contributes exactly 0).
// ---------------------------------------------------------------------------
__global__ void __launch_bounds__(128) rnn_kernel(const float* __restrict__ W_hh,
                                                  const float* __restrict__ b_hh,
                                                  const float* __restrict__ W_out,
                                                  const float* __restrict__ b_out,
                                                  float* __restrict__ out) {
    __shared__ __align__(16) float sh[8][2][16];
    const unsigned FULL = 0xffffffffu;
    int chain = threadIdx.x >> 4;
    int j     = threadIdx.x & 15;
    int jj    = min(j, 14);
    int gid   = blockIdx.x * 8 + chain;

    // packed weights: wX2[p] = (w[2p], w[2p+1]), k=15 padded to 0
    ull wr2[8], wz2[8], wn2[8];
    {
        float wrf[16], wzf[16], wnf[16];
        #pragma unroll
        for (int k = 0; k < 15; ++k) {
            wrf[k] = 0.5f * W_hh[jj * 15 + k];     // pre-halved (sigmoid-via-tanh)
            wzf[k] = 0.5f * W_hh[(15 + jj) * 15 + k];
            wnf[k] = W_hh[(30 + jj) * 15 + k];
        }
        wrf[15] = wzf[15] = wnf[15] = 0.f;
        #pragma unroll
        for (int p = 0; p < 8; ++p) {
            wr2[p] = pk(wrf[2 * p], wrf[2 * p + 1]);
            wz2[p] = pk(wzf[2 * p], wzf[2 * p + 1]);
            wn2[p] = pk(wnf[2 * p], wnf[2 * p + 1]);
        }
    }
    const float bn = b_hh[30 + jj];

    const int* xp = g_xi + (size_t)gid * SEQ;
    const float4* G4 = g_G;
    float4 gc0 = G4[(size_t)clampv(xp[0]) * 16 + j];
    float4 gc1 = G4[(size_t)clampv(xp[1]) * 16 + j];
    float4 gc2 = G4[(size_t)clampv(xp[2]) * 16 + j];

    float h = 0.f;
    #pragma unroll 4
    for (int s = 0; s < SEQ; ++s) {
        int pf = (s + 3 < SEQ) ? s + 3 : SEQ - 1;
        float4 gnew = G4[(size_t)clampv(xp[pf]) * 16 + j];

        int p = s & 1;
        sh[chain][p][j] = h;
        __syncwarp(FULL);
        float4 H0 = *(const float4*)&sh[chain][p][0];
        float4 H1 = *(const float4*)&sh[chain][p][4];
        float4 H2 = *(const float4*)&sh[chain][p][8];
        float4 H3 = *(const float4*)&sh[chain][p][12];
        ull hp0 = pk(H0.x, H0.y), hp1 = pk(H0.z, H0.w);
        ull hp2 = pk(H1.x, H1.y), hp3 = pk(H1.z, H1.w);
        ull hp4 = pk(H2.x, H2.y), hp5 = pk(H2.z, H2.w);
        ull hp6 = pk(H3.x, H3.y), hp7 = pk(H3.z, H3.w);

        ull ra0 = 0, ra1 = 0, za0 = 0, za1 = 0, na0 = 0, na1 = 0;
        ra0 = f2fma(wr2[0], hp0, ra0); ra1 = f2fma(wr2[1], hp1, ra1);
        za0 = f2fma(wz2[0], hp0, za0); za1 = f2fma(wz2[1], hp1, za1);
        na0 = f2fma(wn2[0], hp0, na0); na1 = f2fma(wn2[1], hp1, na1);
        ra0 = f2fma(wr2[2], hp2, ra0); ra1 = f2fma(wr2[3], hp3, ra1);
        za0 = f2fma(wz2[2], hp2, za0); za1 = f2fma(wz2[3], hp3, za1);
        na0 = f2fma(wn2[2], hp2, na0); na1 = f2fma(wn2[3], hp3, na1);
        ra0 = f2fma(wr2[4], hp4, ra0); ra1 = f2fma(wr2[5], hp5, ra1);
        za0 = f2fma(wz2[4], hp4, za0); za1 = f2fma(wz2[5], hp5, za1);
        na0 = f2fma(wn2[4], hp4, na0); na1 = f2fma(wn2[5], hp5, na1);
        ra0 = f2fma(wr2[6], hp6, ra0); ra1 = f2fma(wr2[7], hp7, ra1);
        za0 = f2fma(wz2[6], hp6, za0); za1 = f2fma(wz2[7], hp7, za1);
        na0 = f2fma(wn2[6], hp6, na0); na1 = f2fma(wn2[7], hp7, na1);

        float rlo, rhi, zlo, zhi, nlo, nhi;
        upk(rlo, rhi, f2add(ra0, ra1));
        upk(zlo, zhi, f2add(za0, za1));
        upk(nlo, nhi, f2add(na0, na1));

        float rg = fmaf(0.5f, tanhap(gc0.x + rlo + rhi), 0.5f);
        float zg = fmaf(0.5f, tanhap(gc0.y + zlo + zhi), 0.5f);
        float ns = bn + nlo + nhi;
        float ng = tanhap(fmaf(rg, ns, gc0.z));
        h = fmaf(zg, h - ng, ng);                  // (1-z)*n + z*h

        gc0 = gc1; gc1 = gc2; gc2 = gnew;
    }

    // ---- fused head: final h exchange + logits + softmax over 20 classes ----
    sh[chain][0][j] = h;
    __syncwarp(FULL);
    float hh[15];
    {
        float4 H0 = *(const float4*)&sh[chain][0][0];
        float4 H1 = *(const float4*)&sh[chain][0][4];
        float4 H2 = *(const float4*)&sh[chain][0][8];
        float4 H3 = *(const float4*)&sh[chain][0][12];
        hh[0]=H0.x; hh[1]=H0.y; hh[2]=H0.z; hh[3]=H0.w;
        hh[4]=H1.x; hh[5]=H1.y; hh[6]=H1.z; hh[7]=H1.w;
        hh[8]=H2.x; hh[9]=H2.y; hh[10]=H2.z; hh[11]=H2.w;
        hh[12]=H3.x; hh[13]=H3.y; hh[14]=H3.z;
    }
    float l0 = b_out[j];
    float l1 = (j < 4) ? b_out[16 + j] : -3.0e38f;
    #pragma unroll
    for (int k = 0; k < 15; ++k) {
        l0 = fmaf(W_out[j * 15 + k], hh[k], l0);
        if (j < 4) l1 = fmaf(W_out[(16 + j) * 15 + k], hh[k], l1);
    }
    float m = fmaxf(l0, l1);
    #pragma unroll
    for (int o = 8; o > 0; o >>= 1) m = fmaxf(m, __shfl_xor_sync(FULL, m, o, 16));
    float e0 = __expf(l0 - m);
    float e1 = (j < 4) ? __expf(l1 - m) : 0.f;
    float sum = e0 + e1;
    #pragma unroll
    for (int o = 8; o > 0; o >>= 1) sum += __shfl_xor_sync(FULL, sum, o, 16);
    float inv = __fdividef(1.f, sum);
    out[gid * CDIM + j] = e0 * inv;
    if (j < 4) out[gid * CDIM + 16 + j] = e1 * inv;
}

// ---------------------------------------------------------------------------
extern "C" void kernel_launch(void* const* d_in, const int* in_sizes, int n_in,
                              void* d_out, int out_size) {
    const void*  x     = d_in[0];
    const float* embed = (const float*)d_in[1];
    const float* W_ih  = (const float*)d_in[2];
    const float* b_ih  = (const float*)d_in[3];
    const float* W_hh  = (const float*)d_in[4];
    const float* b_hh  = (const float*)d_in[5];
    const float* W_out = (const float*)d_in[6];
    const float* b_out = (const float*)d_in[7];
    float* out = (float*)d_out;

    gates_kernel<<<(VOCAB + 63) / 64, 256>>>(embed, W_ih, b_ih, b_hh, x);
    rnn_kernel<<<BATCH / 8, 128>>>(W_hh, b_hh, W_out, b_out, out);
}

// round 11
// speedup vs baseline: 1.9547x; 1.2322x over previous
#include <cuda_runtime.h>

#define VOCAB 50000
#define EDIM  128
#define HDIM  15
#define CDIM  20
#define BATCH 512
#define SEQ   512
#define WP    132            // padded W_ih smem pitch (floats)

// G table: [v][j] = {0.5*(r+bhh_r), 0.5*(z+bhh_z), n_part, 0}
__device__ float4 g_G[(size_t)VOCAB * 16];
__device__ int    g_xi[BATCH * SEQ];     // tokens converted to int32

__device__ __forceinline__ float tanhap(float x) {
    float y;
    asm("tanh.approx.f32 %0, %1;" : "=f"(y) : "f"(x));
    return y;
}
__device__ __forceinline__ int clampv(int v) { return min(max(v, 0), VOCAB - 1); }

// ---------------------------------------------------------------------------
// Kernel A: tiled gates GEMM + fused token conversion (first 256 blocks).
// ---------------------------------------------------------------------------
__global__ void __launch_bounds__(256) gates_kernel(const float* __restrict__ embed,
                                                    const float* __restrict__ W_ih,
                                                    const float* __restrict__ b_ih,
                                                    const float* __restrict__ b_hh,
                                                    const void*  __restrict__ xraw) {
    // ---- fused conv: blocks 0..255 convert 1024 tokens each ----
    if (blockIdx.x < 256) {
        __shared__ int s64;
        if (threadIdx.x == 0) {
            const int* xi = (const int*)xraw;
            int ok = 1;
            #pragma unroll
            for (int k = 0; k < 32; ++k)
                if (xi[2 * k + 1] != 0) ok = 0;   // int64 < 2^31 => high words 0
            s64 = ok;
        }
        __syncthreads();
        int i0 = (blockIdx.x * 256 + threadIdx.x) * 4;
        if (s64) {
            const longlong4 v = ((const longlong4*)xraw)[i0 >> 2];
            int4 o;
            o.x = (int)v.x; o.y = (int)v.y; o.z = (int)v.z; o.w = (int)v.w;
            *(int4*)&g_xi[i0] = o;
        } else {
            *(int4*)&g_xi[i0] = *(const int4*)((const int*)xraw + i0);
        }
    }

    // ---- gates GEMM ----
    __shared__ __align__(16) float Wsm[45 * WP];
    for (int i = threadIdx.x; i < 45 * EDIM; i += 256) {
        int r = i >> 7, c = i & 127;
        Wsm[r * WP + c] = W_ih[i];
    }
    __syncthreads();

    int rr = threadIdx.x >> 4;
    int ss = threadIdx.x & 15;
    int sw = min(ss, 14);
    int v0 = blockIdx.x * 64;

    const float4* w0p = (const float4*)&Wsm[sw * WP];
    const float4* w1p = (const float4*)&Wsm[(15 + sw) * WP];
    const float4* w2p = (const float4*)&Wsm[(30 + sw) * WP];

    const float4* ep[4];
    int vr[4];
    #pragma unroll
    for (int i = 0; i < 4; ++i) {
        vr[i] = v0 + rr + 16 * i;
        ep[i] = (const float4*)embed + (size_t)min(vr[i], VOCAB - 1) * 32;
    }

    float ar[4] = {0, 0, 0, 0}, az[4] = {0, 0, 0, 0}, an[4] = {0, 0, 0, 0};
    #pragma unroll 4
    for (int k4 = 0; k4 < 32; ++k4) {
        float4 w0 = w0p[k4], w1 = w1p[k4], w2 = w2p[k4];
        #pragma unroll
        for (int i = 0; i < 4; ++i) {
            float4 a = ep[i][k4];
            ar[i] = fmaf(a.x, w0.x, ar[i]); ar[i] = fmaf(a.y, w0.y, ar[i]);
            ar[i] = fmaf(a.z, w0.z, ar[i]); ar[i] = fmaf(a.w, w0.w, ar[i]);
            az[i] = fmaf(a.x, w1.x, az[i]); az[i] = fmaf(a.y, w1.y, az[i]);
            az[i] = fmaf(a.z, w1.z, az[i]); az[i] = fmaf(a.w, w1.w, az[i]);
            an[i] = fmaf(a.x, w2.x, an[i]); an[i] = fmaf(a.y, w2.y, an[i]);
            an[i] = fmaf(a.z, w2.z, an[i]); an[i] = fmaf(a.w, w2.w, an[i]);
        }
    }

    float bi0 = b_ih[sw] + b_hh[sw];               // fold b_hh into r,z slots
    float bi1 = b_ih[15 + sw] + b_hh[15 + sw];
    float bi2 = b_ih[30 + sw];
    #pragma unroll
    for (int i = 0; i < 4; ++i) {
        if (vr[i] < VOCAB) {
            float4 o;
            o.x = 0.5f * (ar[i] + bi0);            // pre-halved for sigmoid-via-tanh
            o.y = 0.5f * (az[i] + bi1);
            o.z = an[i] + bi2;
            o.w = 0.f;
            if (ss == 15) o = make_float4(0.f, 0.f, 0.f, 0.f);
            g_G[(size_t)vr[i] * 16 + ss] = o;
        }
    }
}

// ---------------------------------------------------------------------------
// Kernel B: GRU recurrence + fused head (R6 structure, deeper prefetch).
// 16 lanes/chain, 8 chains/block, smem double-buffered h exchange.
// G rows prefetched EIGHT steps ahead via a statically-indexed ring so the
// L2 hit latency (~260 cyc) is fully covered; 4-way accumulator split.
// ---------------------------------------------------------------------------
__global__ void __launch_bounds__(128, 1) rnn_kernel(const float* __restrict__ W_hh,
                                                     const float* __restrict__ b_hh,
                                                     const float* __restrict__ W_out,
                                                     const float* __restrict__ b_out,
                                                     float* __restrict__ out) {
    __shared__ __align__(16) float sh[8][2][16];
    const unsigned FULL = 0xffffffffu;
    int chain = threadIdx.x >> 4;
    int j     = threadIdx.x & 15;
    int jj    = min(j, 14);
    int gid   = blockIdx.x * 8 + chain;

    float wr[15], wz[15], wn[15];
    #pragma unroll
    for (int k = 0; k < 15; ++k) {
        wr[k] = 0.5f * W_hh[jj * 15 + k];          // pre-halved (sigmoid-via-tanh)
        wz[k] = 0.5f * W_hh[(15 + jj) * 15 + k];
        wn[k] = W_hh[(30 + jj) * 15 + k];
    }
    const float bn = b_hh[30 + jj];

    const int* xp = g_xi + (size_t)gid * SEQ;
    const float4* G4 = g_G;

    float4 ring[8];
    #pragma unroll
    for (int i = 0; i < 8; ++i)
        ring[i] = G4[(size_t)clampv(xp[i]) * 16 + j];

    float h = 0.f;
    for (int s0 = 0; s0 < SEQ; s0 += 8) {
        #pragma unroll
        for (int u = 0; u < 8; ++u) {
            int s = s0 + u;
            float4 gc = ring[u];
            // prefetch s+8 immediately (consumed 8 steps later)
            int pf = (s + 8 < SEQ) ? s + 8 : SEQ - 1;
            ring[u] = G4[(size_t)clampv(xp[pf]) * 16 + j];

            int p = s & 1;
            sh[chain][p][j] = h;
            __syncwarp(FULL);
            float4 H0 = *(const float4*)&sh[chain][p][0];
            float4 H1 = *(const float4*)&sh[chain][p][4];
            float4 H2 = *(const float4*)&sh[chain][p][8];
            float4 H3 = *(const float4*)&sh[chain][p][12];
            float hh[15] = {H0.x, H0.y, H0.z, H0.w, H1.x, H1.y, H1.z, H1.w,
                            H2.x, H2.y, H2.z, H2.w, H3.x, H3.y, H3.z};

            // 4-way accumulator split: depth 4 FMA + 2 adds per gate
            float r0 = 0.f, r1 = 0.f, r2 = 0.f, r3 = 0.f;
            float z0 = 0.f, z1 = 0.f, z2 = 0.f, z3 = 0.f;
            float n0 = 0.f, n1 = 0.f, n2 = 0.f, n3 = 0.f;
            #pragma unroll
            for (int q = 0; q < 3; ++q) {
                int k0 = q * 4;
                r0 = fmaf(wr[k0 + 0], hh[k0 + 0], r0);
                r1 = fmaf(wr[k0 + 1], hh[k0 + 1], r1);
                r2 = fmaf(wr[k0 + 2], hh[k0 + 2], r2);
                r3 = fmaf(wr[k0 + 3], hh[k0 + 3], r3);
                z0 = fmaf(wz[k0 + 0], hh[k0 + 0], z0);
                z1 = fmaf(wz[k0 + 1], hh[k0 + 1], z1);
                z2 = fmaf(wz[k0 + 2], hh[k0 + 2], z2);
                z3 = fmaf(wz[k0 + 3], hh[k0 + 3], z3);
                n0 = fmaf(wn[k0 + 0], hh[k0 + 0], n0);
                n1 = fmaf(wn[k0 + 1], hh[k0 + 1], n1);
                n2 = fmaf(wn[k0 + 2], hh[k0 + 2], n2);
                n3 = fmaf(wn[k0 + 3], hh[k0 + 3], n3);
            }
            r0 = fmaf(wr[12], hh[12], r0); r1 = fmaf(wr[13], hh[13], r1);
            r2 = fmaf(wr[14], hh[14], r2);
            z0 = fmaf(wz[12], hh[12], z0); z1 = fmaf(wz[13], hh[13], z1);
            z2 = fmaf(wz[14], hh[14], z2);
            n0 = fmaf(wn[12], hh[12], n0); n1 = fmaf(wn[13], hh[13], n1);
            n2 = fmaf(wn[14], hh[14], n2);

            float rsum = (r0 + r1) + (r2 + r3);
            float zsum = (z0 + z1) + (z2 + z3);
            float nsum = (n0 + n1) + (n2 + n3);

            float rg = fmaf(0.5f, tanhap(gc.x + rsum), 0.5f);
            float zg = fmaf(0.5f, tanhap(gc.y + zsum), 0.5f);
            float ng = tanhap(fmaf(rg, bn + nsum, gc.z));
            h = fmaf(zg, h - ng, ng);              // (1-z)*n + z*h
        }
    }

    // ---- fused head: final h exchange + logits + softmax over 20 classes ----
    sh[chain][0][j] = h;
    __syncwarp(FULL);
    float hh[15];
    {
        float4 H0 = *(const float4*)&sh[chain][0][0];
        float4 H1 = *(const float4*)&sh[chain][0][4];
        float4 H2 = *(const float4*)&sh[chain][0][8];
        float4 H3 = *(const float4*)&sh[chain][0][12];
        hh[0]=H0.x; hh[1]=H0.y; hh[2]=H0.z; hh[3]=H0.w;
        hh[4]=H1.x; hh[5]=H1.y; hh[6]=H1.z; hh[7]=H1.w;
        hh[8]=H2.x; hh[9]=H2.y; hh[10]=H2.z; hh[11]=H2.w;
        hh[12]=H3.x; hh[13]=H3.y; hh[14]=H3.z;
    }
    float l0 = b_out[j];
    float l1 = (j < 4) ? b_out[16 + j] : -3.0e38f;
    #pragma unroll
    for (int k = 0; k < 15; ++k) {
        l0 = fmaf(W_out[j * 15 + k], hh[k], l0);
        if (j < 4) l1 = fmaf(W_out[(16 + j) * 15 + k], hh[k], l1);
    }
    float m = fmaxf(l0, l1);
    #pragma unroll
    for (int o = 8; o > 0; o >>= 1) m = fmaxf(m, __shfl_xor_sync(FULL, m, o, 16));
    float e0 = __expf(l0 - m);
    float e1 = (j < 4) ? __expf(l1 - m) : 0.f;
    float sum = e0 + e1;
    #pragma unroll
    for (int o = 8; o > 0; o >>= 1) sum += __shfl_xor_sync(FULL, sum, o, 16);
    float inv = __fdividef(1.f, sum);
    out[gid * CDIM + j] = e0 * inv;
    if (j < 4) out[gid * CDIM + 16 + j] = e1 * inv;
}

// ---------------------------------------------------------------------------
extern "C" void kernel_launch(void* const* d_in, const int* in_sizes, int n_in,
                              void* d_out, int out_size) {
    const void*  x     = d_in[0];
    const float* embed = (const float*)d_in[1];
    const float* W_ih  = (const float*)d_in[2];
    const float* b_ih  = (const float*)d_in[3];
    const float* W_hh  = (const float*)d_in[4];
    const float* b_hh  = (const float*)d_in[5];
    const float* W_out = (const float*)d_in[6];
    const float* b_out = (const float*)d_in[7];
    float* out = (float*)d_out;

    gates_kernel<<<(VOCAB + 63) / 64, 256>>>(embed, W_ih, b_ih, b_hh, x);
    rnn_kernel<<<BATCH / 8, 128>>>(W_hh, b_hh, W_out, b_out, out);
}